// round 16
// baseline (speedup 1.0000x reference)
#include <cuda_runtime.h>
#include <cstdint>

// TPThird: per-sample equivariant tensor product. NS=48, NV=10, Z=50000.
// x1: (Z,108) = [0e:48 | 1o:10x3 | 1e:10x3]
// x2: (Z,9)   = [0e:1 | 1o:3 | 2e:5]
// weights: (Z,4344), out: (Z,156) = [r0e:48 | r1o:30 | r1e:30 | r0o:48]
//
// Converged HBM-streaming kernel + one-wave-ahead L2 prefetch: each block
// prefetches the weight row of sample z+1480 (148 SMs x 10 blocks = 1 wave)
// into L2, so its successor's TMA hits L2 instead of paying a DRAM round
// trip at block start. W row via cp.async.bulk with L2::evict_first;
// x1/x2 via __ldcs; outputs via __stcs; warp-balanced contraction
// (p01 on warp 5 -> warp 2 via named barrier 1).

#define X1DIM 108
#define WNUM  4344
#define OUTDIM 156

#define OW00  0
#define OW01  2304
#define OW10  2784
#define OW110 2884
#define OW112 3364
#define OW12  3464
#define OW20  3564
#define OW211 3664
#define OW213 3764
#define OW22  4244

#define WAVE_AHEAD 1480   // 148 SMs * 10 blocks/SM

__device__ __forceinline__ uint32_t smem_u32(const void* p) {
    return (uint32_t)__cvta_generic_to_shared(p);
}

__device__ __forceinline__ void mbar_wait(uint32_t mb, uint32_t phase) {
    uint32_t done;
    asm volatile(
        "{\n\t"
        ".reg .pred P;\n\t"
        "WAIT_%=:\n\t"
        "mbarrier.try_wait.parity.shared.b64 P, [%1], %2;\n\t"
        "selp.b32 %0, 1, 0, P;\n\t"
        "@!P bra WAIT_%=;\n\t"
        "}"
        : "=r"(done) : "r"(mb), "r"(phase) : "memory");
}

__global__ __launch_bounds__(192, 10)
void tpthird_kernel(const float* __restrict__ x1,
                    const float* __restrict__ x2,
                    const float* __restrict__ W,
                    float* __restrict__ out,
                    int Z)
{
    const int z   = blockIdx.x;
    const int tid = threadIdx.x;
    const int wid = tid >> 5;
    const int lid = tid & 31;

    __shared__ __align__(16) float s_W[WNUM];
    __shared__ __align__(16) float s_x1[X1DIM];
    __shared__ float s_x2[9];
    __shared__ float s_d1o[2][10];                 // warps 0,1
    __shared__ float s_d1e[2][10];                 // warps 4,5
    __shared__ float s_t12[10][3], s_t211[10][3];  // warp 2
    __shared__ float s_t112[10][3], s_t22[10][3];  // warp 3
    __shared__ float s_p01[10];                    // warp 5 -> warp 2
    __shared__ __align__(8) unsigned long long s_mbar;

    const uint32_t mb = smem_u32(&s_mbar);

    // tid 0: init barrier, launch the W-row TMA (evict-first), then prefetch
    // the weight row one wave ahead into L2.
    if (tid == 0) {
        asm volatile("mbarrier.init.shared.b64 [%0], 1;" :: "r"(mb) : "memory");
        asm volatile("fence.proxy.async.shared::cta;" ::: "memory");
        asm volatile("mbarrier.arrive.expect_tx.shared.b64 _, [%0], %1;"
                     :: "r"(mb), "r"((uint32_t)(WNUM * 4)) : "memory");
        uint64_t pol;
        asm volatile("createpolicy.fractional.L2::evict_first.b64 %0, 1.0;"
                     : "=l"(pol));
        asm volatile("cp.async.bulk.shared::cta.global.mbarrier::complete_tx::bytes"
                     ".L2::cache_hint [%0], [%1], %2, [%3], %4;"
                     :: "r"(smem_u32(s_W)), "l"(W + (size_t)z * WNUM),
                        "r"((uint32_t)(WNUM * 4)), "r"(mb), "l"(pol) : "memory");
        const int zp = z + WAVE_AHEAD;
        if (zp < Z) {
            asm volatile("cp.async.bulk.prefetch.L2.global.L2::cache_hint "
                         "[%0], %1, %2;"
                         :: "l"(W + (size_t)zp * WNUM),
                            "r"((uint32_t)(WNUM * 4)), "l"(pol) : "memory");
        }
    }
    // x1/x2 via streaming LDG (concurrent with the TMA stream).
    if (tid < X1DIM) {
        s_x1[tid] = __ldcs(x1 + (size_t)z * X1DIM + tid);
    } else if (tid < X1DIM + 9) {
        s_x2[tid - X1DIM] = __ldcs(x2 + (size_t)z * 9 + (tid - X1DIM));
    }
    __syncthreads();   // covers: mbar init, s_x1, s_x2

    const float N0E  = 0.1313064328597226f;    // sqrt(1/58)
    const float N1O  = 0.1961161351381841f;    // sqrt(3/78)
    const float N1E  = 0.3162277660168379f;    // sqrt(1/10)
    const float N0O  = 0.3162277660168379f;    // sqrt(1/10)
    const float ISQ3 = 0.5773502691896258f;    // 1/sqrt(3)
    const float IS6  = 0.4082482904638630164f; // 1/sqrt(6)
    const float S10  = 0.3162277660168379332f; // 1/sqrt(10)
    const float S30  = 0.1825741858350553712f; // 1/sqrt(30)

    const float x20 = s_x2[0];
    const float b0 = s_x2[1], b1 = s_x2[2], b2 = s_x2[3];

    // ---- per-warp precompute (overlaps the TMA wait), lanes 0-9 ----
    if (wid < 2) {
        if (lid < 10) {
            const int u = lid;
            s_d1o[wid][u] = s_x1[48 + u*3 + 0]*b0 + s_x1[48 + u*3 + 1]*b1
                          + s_x1[48 + u*3 + 2]*b2;
        }
    } else if (wid == 2) {
        if (lid < 10) {
            const int u = lid;
            const float a0 = s_x1[48 + u*3 + 0];
            const float a1 = s_x1[48 + u*3 + 1];
            const float a2 = s_x1[48 + u*3 + 2];
            const float e0 = s_x1[78 + u*3 + 0];
            const float e1 = s_x1[78 + u*3 + 1];
            const float e2 = s_x1[78 + u*3 + 2];
            const float c0 = s_x2[4], c1 = s_x2[5], c2 = s_x2[6];
            const float c3 = s_x2[7], c4 = s_x2[8];
            s_t211[u][0] = (e1*b2 - e2*b1) * IS6;
            s_t211[u][1] = (e2*b0 - e0*b2) * IS6;
            s_t211[u][2] = (e0*b1 - e1*b0) * IS6;
            s_t12[u][0] =  S10*a2*c0 - S30*a0*c2 - S10*a0*c4 + S10*a1*c1;
            s_t12[u][1] =  S10*a2*c3 + S10*a0*c1 + 2.0f*S30*a1*c2;
            s_t12[u][2] = -S30*a2*c2 + S10*a2*c4 + S10*a0*c0 + S10*a1*c3;
        }
    } else if (wid == 3) {
        if (lid < 10) {
            const int u = lid;
            const float a0 = s_x1[48 + u*3 + 0];
            const float a1 = s_x1[48 + u*3 + 1];
            const float a2 = s_x1[48 + u*3 + 2];
            const float e0 = s_x1[78 + u*3 + 0];
            const float e1 = s_x1[78 + u*3 + 1];
            const float e2 = s_x1[78 + u*3 + 2];
            const float c0 = s_x2[4], c1 = s_x2[5], c2 = s_x2[6];
            const float c3 = s_x2[7], c4 = s_x2[8];
            s_t112[u][0] = (a1*b2 - a2*b1) * IS6;
            s_t112[u][1] = (a2*b0 - a0*b2) * IS6;
            s_t112[u][2] = (a0*b1 - a1*b0) * IS6;
            s_t22[u][0] =  S10*e2*c0 - S30*e0*c2 - S10*e0*c4 + S10*e1*c1;
            s_t22[u][1] =  S10*e2*c3 + S10*e0*c1 + 2.0f*S30*e1*c2;
            s_t22[u][2] = -S30*e2*c2 + S10*e2*c4 + S10*e0*c0 + S10*e1*c3;
        }
    } else {
        if (lid < 10) {
            const int u = lid;
            s_d1e[wid - 4][u] = s_x1[78 + u*3 + 0]*b0 + s_x1[78 + u*3 + 1]*b1
                              + s_x1[78 + u*3 + 2]*b2;
        }
    }
    __syncwarp();

    mbar_wait(mb, 0);   // weights landed

    float* __restrict__ oz = out + (size_t)z * OUTDIM;

    // ---- weight contraction ----
    // warps 0-1 -> r0e (48/64 lanes, 58 it) | warp 2 -> r1o (30 it, waits bar1)
    // warp 3 -> r1e (30 it) | warp 4 -> r0o[0..31] (10 it)
    // warp 5 -> p01 (48 it, lanes 0-9) + bar1.arrive + r0o[32..47] (10 it)
    if (wid < 2) {
        const int w = tid;
        if (w < 48) {
            float acc = 0.0f;
            #pragma unroll
            for (int u = 0; u < 48; u++)
                acc += s_x1[u] * s_W[OW00 + u*48 + w];
            acc *= x20;
            float acc2 = 0.0f;
            #pragma unroll
            for (int u = 0; u < 10; u++)
                acc2 += s_d1o[wid][u] * s_W[OW110 + u*48 + w];
            __stcs(&oz[w], N0E * (acc + ISQ3 * acc2));
        }
    } else if (wid == 2) {
        // wait for warp 5's p01
        asm volatile("bar.sync 1, 64;" ::: "memory");
        if (lid < 30) {
            const int w = lid / 3, j = lid % 3;
            const float x2j = s_x2[1 + j];
            const float p01 = s_p01[w];
            float a10 = 0.0f, a12 = 0.0f, a211 = 0.0f;
            #pragma unroll
            for (int u = 0; u < 10; u++) {
                a10  += s_x1[48 + u*3 + j] * s_W[OW10  + u*10 + w];
                a12  += s_t12[u][j]        * s_W[OW12  + u*10 + w];
                a211 += s_t211[u][j]       * s_W[OW211 + u*10 + w];
            }
            __stcs(&oz[48 + lid],
                   N1O * (ISQ3 * (x2j * p01 + x20 * a10) + a12 + a211));
        }
    } else if (wid == 3) {
        if (lid < 30) {
            const int w = lid / 3, k = lid % 3;
            float a112 = 0.0f, a20 = 0.0f, a22 = 0.0f;
            #pragma unroll
            for (int u = 0; u < 10; u++) {
                a112 += s_t112[u][k]       * s_W[OW112 + u*10 + w];
                a20  += s_x1[78 + u*3 + k] * s_W[OW20  + u*10 + w];
                a22  += s_t22[u][k]        * s_W[OW22  + u*10 + w];
            }
            __stcs(&oz[78 + lid], N1E * (a112 + ISQ3 * x20 * a20 + a22));
        }
    } else if (wid == 4) {
        const int w = lid;          // r0o[0..31]
        float acc = 0.0f;
        #pragma unroll
        for (int u = 0; u < 10; u++)
            acc += s_d1e[0][u] * s_W[OW213 + u*48 + w];
        __stcs(&oz[108 + w], N0O * ISQ3 * acc);
    } else {
        // warp 5: p01 for warp 2, then its r0o slice
        if (lid < 10) {
            const int w = lid;
            float p = 0.0f;
            #pragma unroll
            for (int u = 0; u < 48; u++)
                p += s_x1[u] * s_W[OW01 + u*10 + w];
            s_p01[w] = p;
        }
        asm volatile("bar.arrive 1, 64;" ::: "memory");
        if (lid < 16) {
            const int w = 32 + lid;  // r0o[32..47]
            float acc = 0.0f;
            #pragma unroll
            for (int u = 0; u < 10; u++)
                acc += s_d1e[1][u] * s_W[OW213 + u*48 + w];
            __stcs(&oz[108 + w], N0O * ISQ3 * acc);
        }
    }
}

extern "C" void kernel_launch(void* const* d_in, const int* in_sizes, int n_in,
                              void* d_out, int out_size)
{
    const float* x1 = (const float*)d_in[0];
    const float* x2 = (const float*)d_in[1];
    const float* W  = (const float*)d_in[2];
    float* out = (float*)d_out;

    const int Z = in_sizes[0] / X1DIM;
    tpthird_kernel<<<Z, 192>>>(x1, x2, W, out, Z);
}

// round 17
// speedup vs baseline: 1.1014x; 1.1014x over previous
#include <cuda_runtime.h>
#include <cstdint>

// TPThird: per-sample equivariant tensor product. NS=48, NV=10, Z=50000.
// x1: (Z,108) = [0e:48 | 1o:10x3 | 1e:10x3]
// x2: (Z,9)   = [0e:1 | 1o:3 | 2e:5]
// weights: (Z,4344), out: (Z,156) = [r0e:48 | r1o:30 | r1e:30 | r0o:48]
//
// FINAL converged kernel (HBM-streaming roofline: ~7.0 TB/s delivered on a
// 923 MB single-use weight stream). One 192-thread block per sample (10/SM,
// each an independent TMA stream — block-count concurrency beats
// bytes-per-block on this workload). W row via cp.async.bulk with
// L2::evict_first (single-use stream, keeps LTS clean); x1/x2 via __ldcs
// pre-sync so all derived activations overlap the TMA wait; outputs via
// __stcs. Warp-balanced contraction: the 48-iter w01 loop (p01) lives on
// otherwise-idle warp 5 and is handed to warp 2 via named barrier 1,
// keeping the block critical path at ~58 MAC iterations.

#define X1DIM 108
#define WNUM  4344
#define OUTDIM 156

#define OW00  0
#define OW01  2304
#define OW10  2784
#define OW110 2884
#define OW112 3364
#define OW12  3464
#define OW20  3564
#define OW211 3664
#define OW213 3764
#define OW22  4244

__device__ __forceinline__ uint32_t smem_u32(const void* p) {
    return (uint32_t)__cvta_generic_to_shared(p);
}

__device__ __forceinline__ void mbar_wait(uint32_t mb, uint32_t phase) {
    uint32_t done;
    asm volatile(
        "{\n\t"
        ".reg .pred P;\n\t"
        "WAIT_%=:\n\t"
        "mbarrier.try_wait.parity.shared.b64 P, [%1], %2;\n\t"
        "selp.b32 %0, 1, 0, P;\n\t"
        "@!P bra WAIT_%=;\n\t"
        "}"
        : "=r"(done) : "r"(mb), "r"(phase) : "memory");
}

__global__ __launch_bounds__(192, 10)
void tpthird_kernel(const float* __restrict__ x1,
                    const float* __restrict__ x2,
                    const float* __restrict__ W,
                    float* __restrict__ out)
{
    const int z   = blockIdx.x;
    const int tid = threadIdx.x;
    const int wid = tid >> 5;
    const int lid = tid & 31;

    __shared__ __align__(16) float s_W[WNUM];
    __shared__ __align__(16) float s_x1[X1DIM];
    __shared__ float s_x2[9];
    __shared__ float s_d1o[2][10];                 // warps 0,1
    __shared__ float s_d1e[2][10];                 // warps 4,5
    __shared__ float s_t12[10][3], s_t211[10][3];  // warp 2
    __shared__ float s_t112[10][3], s_t22[10][3];  // warp 3
    __shared__ float s_p01[10];                    // warp 5 -> warp 2
    __shared__ __align__(8) unsigned long long s_mbar;

    const uint32_t mb = smem_u32(&s_mbar);

    // tid 0: init barrier and launch the W-row TMA with evict-first policy.
    if (tid == 0) {
        asm volatile("mbarrier.init.shared.b64 [%0], 1;" :: "r"(mb) : "memory");
        asm volatile("fence.proxy.async.shared::cta;" ::: "memory");
        asm volatile("mbarrier.arrive.expect_tx.shared.b64 _, [%0], %1;"
                     :: "r"(mb), "r"((uint32_t)(WNUM * 4)) : "memory");
        uint64_t pol;
        asm volatile("createpolicy.fractional.L2::evict_first.b64 %0, 1.0;"
                     : "=l"(pol));
        asm volatile("cp.async.bulk.shared::cta.global.mbarrier::complete_tx::bytes"
                     ".L2::cache_hint [%0], [%1], %2, [%3], %4;"
                     :: "r"(smem_u32(s_W)), "l"(W + (size_t)z * WNUM),
                        "r"((uint32_t)(WNUM * 4)), "r"(mb), "l"(pol) : "memory");
    }
    // x1/x2 via streaming LDG (concurrent with the TMA stream).
    if (tid < X1DIM) {
        s_x1[tid] = __ldcs(x1 + (size_t)z * X1DIM + tid);
    } else if (tid < X1DIM + 9) {
        s_x2[tid - X1DIM] = __ldcs(x2 + (size_t)z * 9 + (tid - X1DIM));
    }
    __syncthreads();   // covers: mbar init, s_x1, s_x2

    const float N0E  = 0.1313064328597226f;    // sqrt(1/58)
    const float N1O  = 0.1961161351381841f;    // sqrt(3/78)
    const float N1E  = 0.3162277660168379f;    // sqrt(1/10)
    const float N0O  = 0.3162277660168379f;    // sqrt(1/10)
    const float ISQ3 = 0.5773502691896258f;    // 1/sqrt(3)
    const float IS6  = 0.4082482904638630164f; // 1/sqrt(6)
    const float S10  = 0.3162277660168379332f; // 1/sqrt(10)
    const float S30  = 0.1825741858350553712f; // 1/sqrt(30)

    const float x20 = s_x2[0];
    const float b0 = s_x2[1], b1 = s_x2[2], b2 = s_x2[3];

    // ---- per-warp precompute (overlaps the TMA wait), lanes 0-9 ----
    if (wid < 2) {
        if (lid < 10) {
            const int u = lid;
            s_d1o[wid][u] = s_x1[48 + u*3 + 0]*b0 + s_x1[48 + u*3 + 1]*b1
                          + s_x1[48 + u*3 + 2]*b2;
        }
    } else if (wid == 2) {
        if (lid < 10) {
            const int u = lid;
            const float a0 = s_x1[48 + u*3 + 0];
            const float a1 = s_x1[48 + u*3 + 1];
            const float a2 = s_x1[48 + u*3 + 2];
            const float e0 = s_x1[78 + u*3 + 0];
            const float e1 = s_x1[78 + u*3 + 1];
            const float e2 = s_x1[78 + u*3 + 2];
            const float c0 = s_x2[4], c1 = s_x2[5], c2 = s_x2[6];
            const float c3 = s_x2[7], c4 = s_x2[8];
            s_t211[u][0] = (e1*b2 - e2*b1) * IS6;
            s_t211[u][1] = (e2*b0 - e0*b2) * IS6;
            s_t211[u][2] = (e0*b1 - e1*b0) * IS6;
            s_t12[u][0] =  S10*a2*c0 - S30*a0*c2 - S10*a0*c4 + S10*a1*c1;
            s_t12[u][1] =  S10*a2*c3 + S10*a0*c1 + 2.0f*S30*a1*c2;
            s_t12[u][2] = -S30*a2*c2 + S10*a2*c4 + S10*a0*c0 + S10*a1*c3;
        }
    } else if (wid == 3) {
        if (lid < 10) {
            const int u = lid;
            const float a0 = s_x1[48 + u*3 + 0];
            const float a1 = s_x1[48 + u*3 + 1];
            const float a2 = s_x1[48 + u*3 + 2];
            const float e0 = s_x1[78 + u*3 + 0];
            const float e1 = s_x1[78 + u*3 + 1];
            const float e2 = s_x1[78 + u*3 + 2];
            const float c0 = s_x2[4], c1 = s_x2[5], c2 = s_x2[6];
            const float c3 = s_x2[7], c4 = s_x2[8];
            s_t112[u][0] = (a1*b2 - a2*b1) * IS6;
            s_t112[u][1] = (a2*b0 - a0*b2) * IS6;
            s_t112[u][2] = (a0*b1 - a1*b0) * IS6;
            s_t22[u][0] =  S10*e2*c0 - S30*e0*c2 - S10*e0*c4 + S10*e1*c1;
            s_t22[u][1] =  S10*e2*c3 + S10*e0*c1 + 2.0f*S30*e1*c2;
            s_t22[u][2] = -S30*e2*c2 + S10*e2*c4 + S10*e0*c0 + S10*e1*c3;
        }
    } else {
        if (lid < 10) {
            const int u = lid;
            s_d1e[wid - 4][u] = s_x1[78 + u*3 + 0]*b0 + s_x1[78 + u*3 + 1]*b1
                              + s_x1[78 + u*3 + 2]*b2;
        }
    }
    __syncwarp();

    mbar_wait(mb, 0);   // weights landed

    float* __restrict__ oz = out + (size_t)z * OUTDIM;

    // ---- weight contraction ----
    // warps 0-1 -> r0e (48/64 lanes, 58 it) | warp 2 -> r1o (30 it, waits bar1)
    // warp 3 -> r1e (30 it) | warp 4 -> r0o[0..31] (10 it)
    // warp 5 -> p01 (48 it, lanes 0-9) + bar1.arrive + r0o[32..47] (10 it)
    if (wid < 2) {
        const int w = tid;
        if (w < 48) {
            float acc = 0.0f;
            #pragma unroll
            for (int u = 0; u < 48; u++)
                acc += s_x1[u] * s_W[OW00 + u*48 + w];
            acc *= x20;
            float acc2 = 0.0f;
            #pragma unroll
            for (int u = 0; u < 10; u++)
                acc2 += s_d1o[wid][u] * s_W[OW110 + u*48 + w];
            __stcs(&oz[w], N0E * (acc + ISQ3 * acc2));
        }
    } else if (wid == 2) {
        // wait for warp 5's p01
        asm volatile("bar.sync 1, 64;" ::: "memory");
        if (lid < 30) {
            const int w = lid / 3, j = lid % 3;
            const float x2j = s_x2[1 + j];
            const float p01 = s_p01[w];
            float a10 = 0.0f, a12 = 0.0f, a211 = 0.0f;
            #pragma unroll
            for (int u = 0; u < 10; u++) {
                a10  += s_x1[48 + u*3 + j] * s_W[OW10  + u*10 + w];
                a12  += s_t12[u][j]        * s_W[OW12  + u*10 + w];
                a211 += s_t211[u][j]       * s_W[OW211 + u*10 + w];
            }
            __stcs(&oz[48 + lid],
                   N1O * (ISQ3 * (x2j * p01 + x20 * a10) + a12 + a211));
        }
    } else if (wid == 3) {
        if (lid < 30) {
            const int w = lid / 3, k = lid % 3;
            float a112 = 0.0f, a20 = 0.0f, a22 = 0.0f;
            #pragma unroll
            for (int u = 0; u < 10; u++) {
                a112 += s_t112[u][k]       * s_W[OW112 + u*10 + w];
                a20  += s_x1[78 + u*3 + k] * s_W[OW20  + u*10 + w];
                a22  += s_t22[u][k]        * s_W[OW22  + u*10 + w];
            }
            __stcs(&oz[78 + lid], N1E * (a112 + ISQ3 * x20 * a20 + a22));
        }
    } else if (wid == 4) {
        const int w = lid;          // r0o[0..31]
        float acc = 0.0f;
        #pragma unroll
        for (int u = 0; u < 10; u++)
            acc += s_d1e[0][u] * s_W[OW213 + u*48 + w];
        __stcs(&oz[108 + w], N0O * ISQ3 * acc);
    } else {
        // warp 5: p01 for warp 2, then its r0o slice
        if (lid < 10) {
            const int w = lid;
            float p = 0.0f;
            #pragma unroll
            for (int u = 0; u < 48; u++)
                p += s_x1[u] * s_W[OW01 + u*10 + w];
            s_p01[w] = p;
        }
        asm volatile("bar.arrive 1, 64;" ::: "memory");
        if (lid < 16) {
            const int w = 32 + lid;  // r0o[32..47]
            float acc = 0.0f;
            #pragma unroll
            for (int u = 0; u < 10; u++)
                acc += s_d1e[1][u] * s_W[OW213 + u*48 + w];
            __stcs(&oz[108 + w], N0O * ISQ3 * acc);
        }
    }
}

extern "C" void kernel_launch(void* const* d_in, const int* in_sizes, int n_in,
                              void* d_out, int out_size)
{
    const float* x1 = (const float*)d_in[0];
    const float* x2 = (const float*)d_in[1];
    const float* W  = (const float*)d_in[2];
    float* out = (float*)d_out;

    const int Z = in_sizes[0] / X1DIM;
    tpthird_kernel<<<Z, 192>>>(x1, x2, W, out);
}